// round 13
// baseline (speedup 1.0000x reference)
#include <cuda_runtime.h>
#include <math.h>

#define Bs   16
#define Cc   256
#define Hh   128
#define Ww   128
#define HW   16384
#define NSLC 4           // ping-pong scratch slices / streams
#define PIX  32          // pixels per scatter block
#define SS   258         // smem row stride (words): even -> 8B-aligned LDS.64
#define EPSV 1e-05f
#define DPIX 16          // pixels per div block
#define DSTRIDE 544      // words per div tile (16*34) — 544%32==0, phases clean

// FOUR ping-pong scratch slices [NSLC][HW][C] (16 MB each, 64 MB total,
// L2-resident): batch c uses slice c%4 on stream c%4. g_att full size
// [Bs][HW] (batch-disjoint). Zero-initialized at load; k_div restores zeros
// after consumption (separate pass AFTER reads complete — R3 lesson: never
// store to a line with a pending same-thread load miss), so graph replays
// are deterministic. Streaming data (x, out, offo) uses evict-first hints
// (__ldcs/__stcs) so it cannot evict scratch from L2.
__device__ float g_feat[(size_t)NSLC * HW * Cc];
__device__ float g_att[(size_t)Bs * HW];

// -------------------------------------------- fused conv + scatter
// NUMERICS FROZEN (R8/R9 lesson): the strided-by-8 fp32 summation order
// (warp w owns channels {8k+w}, serial fmaf over k; per-pixel reduce in
// w-order seeded with cb) correlates with the reference's own fp32 rounding
// at the round(dest) boundaries -> rel_err 8.8778e-4 stable. Do not reorder.
// R12 change: ALL warps redundantly compute the (identical) reduce/exp/idx
// for pixel=lane — removes the warp0-serial bubble + one barrier; scatter
// gets att/idx via shfl instead of smem.
__global__ __launch_bounds__(256) void k_scatter(
    const float* __restrict__ x, const float* __restrict__ cw,
    const float* __restrict__ cb, float* __restrict__ offo, int b, int slc) {
    __shared__ float s_x[PIX * SS];     // 33 KB tile, [pixel][channel]
    __shared__ float s_w[3 * Cc];
    __shared__ float s_red[3 * 8 * 32];

    const int tid  = threadIdx.x;
    const int lane = tid & 31;
    const int warp = tid >> 5;
    const int hw0  = blockIdx.x * PIX;
    float* feat = g_feat + (size_t)slc * HW * Cc;

    for (int i = tid; i < 3 * Cc; i += 256) s_w[i] = cw[i];
    __syncthreads();

    const float* xb = x + (size_t)b * Cc * HW + hw0;
    float a0 = 0.f, a1 = 0.f, a2 = 0.f;
#pragma unroll
    for (int k = 0; k < Cc / 8; k++) {
        int c = k * 8 + warp;                         // warp owns channel slice
        float v = __ldcs(xb + (size_t)c * HW + lane); // streaming: read-once x
        s_x[lane * SS + c] = v;
        a0 = fmaf(v, s_w[c],          a0);
        a1 = fmaf(v, s_w[Cc + c],     a1);
        a2 = fmaf(v, s_w[2 * Cc + c], a2);
    }
    s_red[(0 * 8 + warp) * 32 + lane] = a0;
    s_red[(1 * 8 + warp) * 32 + lane] = a1;
    s_red[(2 * 8 + warp) * 32 + lane] = a2;
    __syncthreads();

    // Every warp computes the identical per-pixel (pixel = lane) reduce.
    float r0 = cb[0], r1 = cb[1], r2 = cb[2];
#pragma unroll
    for (int w = 0; w < 8; w++) {
        r0 += s_red[w * 32 + lane];
        r1 += s_red[(8 + w) * 32 + lane];
        r2 += s_red[(16 + w) * 32 + lane];
    }
    const float offy = r0 * (float)Hh;
    const float offx = r1 * (float)Ww;
    const float att  = expf(r2);
    {
        int hw = hw0 + lane;
        int hh = hw >> 7, wc = hw & 127;
        // round-half-even (rintf) then clip, matching jnp.round + clip
        int iy = (int)fminf(fmaxf(rintf((float)hh + offy), 0.f), 127.f);
        int ix = (int)fminf(fmaxf(rintf((float)wc + offx), 0.f), 127.f);
        const int idx = (iy << 7) + ix;

        if (warp == 0) {                // single writer for offo / g_att
            size_t ob = (size_t)b * 2 * HW + hw;   // offset: [B][2][H][W]
            __stcs(offo + ob,      offy);          // streaming: write-once
            __stcs(offo + ob + HW, offx);
            atomicAdd(&g_att[(size_t)b * HW + idx], att);
        }

        // Scatter: each warp handles 4 pixels; att/idx via shfl broadcast.
#pragma unroll
        for (int p = warp; p < PIX; p += 8) {
            const float attp = __shfl_sync(0xffffffffu, att, p);
            const int   idxp = __shfl_sync(0xffffffffu, idx, p);
            float* dst = feat + (size_t)idxp * Cc;
            const float* src = s_x + p * SS;
#pragma unroll
            for (int r = 0; r < 2; r++) {
                int c0 = r * 128 + 4 * lane;
                float2 u = *reinterpret_cast<const float2*>(src + c0);
                float2 v = *reinterpret_cast<const float2*>(src + c0 + 2);
                asm volatile(
                    "red.global.add.v4.f32 [%0], {%1, %2, %3, %4};" ::
                    "l"(dst + c0),
                    "f"(u.x * attp), "f"(u.y * attp),
                    "f"(v.x * attp), "f"(v.y * attp)
                    : "memory");
            }
        }
    }
}

// ----------------- normalize + transpose to [B][C][HW] + re-zero scratch
// 128-thread / 16-pixel blocks (smem 17.4 KB -> ~13 blocks/SM, 52 warps).
// Load: 8 independent coalesced LDG.128/thread into 8 stride-34 tiles
// (16 hw x 32 ch each); ONE barrier. Store: warp handles 2 channel groups;
// lane (q=l>>3, jl=l&7) gathers 4 hw per channel (banks 8q+jl: conflict-
// free) and writes streaming STG.128. Zero pass after consumption.
__global__ __launch_bounds__(128) void k_div(float* __restrict__ out, int b,
                                             int slc) {
    __shared__ float t[8 * DSTRIDE];    // 17 KB
    __shared__ __align__(16) float inv[DPIX];
    const int tid = threadIdx.x;
    const int hw0 = blockIdx.x * DPIX;
    float* feat = g_feat + (size_t)slc * HW * Cc;

    if (tid < DPIX)
        inv[tid] = 1.0f / (g_att[(size_t)b * HW + hw0 + tid] + EPSV);

    const float4* src = reinterpret_cast<const float4*>(feat + (size_t)hw0 * Cc);
#pragma unroll
    for (int k = 0; k < 8; k++) {
        int i  = tid + k * 128;         // [0, 1024)
        int hw = i >> 6;                // 0..15 (pixel)
        int cq = i & 63;                // float4 index within 256 channels
        float4 v = src[i];
        int g  = cq >> 3;               // channel group (tile)
        int cc = (cq & 7) * 4;          // channel within tile
        float* d = &t[g * DSTRIDE + hw * 34 + cc];
        d[0] = v.x; d[1] = v.y; d[2] = v.z; d[3] = v.w;
    }
    __syncthreads();

    const int lane = tid & 31;
    const int warp = tid >> 5;          // 4 warps, 2 channel groups each
    const int q    = lane >> 3;         // hw quad (4q..4q+3)
    const int jl   = lane & 7;          // channel sub-lane
    const float4 iv = *reinterpret_cast<const float4*>(&inv[4 * q]);
#pragma unroll
    for (int h = 0; h < 2; h++) {
        const int g = warp * 2 + h;
        const float* tg = &t[g * DSTRIDE];
#pragma unroll
        for (int it = 0; it < 4; it++) {
            const int cc = it * 8 + jl; // channel within group
            float4 o;
            o.x = tg[(4 * q + 0) * 34 + cc] * iv.x;
            o.y = tg[(4 * q + 1) * 34 + cc] * iv.y;
            o.z = tg[(4 * q + 2) * 34 + cc] * iv.z;
            o.w = tg[(4 * q + 3) * 34 + cc] * iv.w;
            __stcs(reinterpret_cast<float4*>(
                out + ((size_t)b * Cc + g * 32 + cc) * HW + hw0 + 4 * q), o);
        }
    }

    // Re-zero this block's scratch region (all loads above completed).
    float4* fz = reinterpret_cast<float4*>(feat + (size_t)hw0 * Cc);
    float4 z = make_float4(0.f, 0.f, 0.f, 0.f);
#pragma unroll
    for (int k = 0; k < 8; k++)
        fz[tid + k * 128] = z;
    if (tid < DPIX)
        g_att[(size_t)b * HW + hw0 + tid] = 0.f;
}

// ---------------------------------------------------------------- launch
// 16 independent (scatter,div) pairs, one batch each, round-robin over 4
// streams (origin + 3) with capture-safe event fork/join. Scratch slice
// reuse within a stream is ordered by stream order.
extern "C" void kernel_launch(void* const* d_in, const int* in_sizes, int n_in,
                              void* d_out, int out_size) {
    const float* x  = (const float*)d_in[0];   // [16,256,128,128]
    const float* cw = (const float*)d_in[1];   // [3,256]
    const float* cb = (const float*)d_in[2];   // [3]
    float* out  = (float*)d_out;                        // [B,C,HW]
    float* offo = out + (size_t)Bs * Cc * HW;           // [B,2,H,W]

    static cudaStream_t st[NSLC] = {nullptr, nullptr, nullptr, nullptr};
    static cudaEvent_t  efork = nullptr;
    static cudaEvent_t  ejoin[NSLC] = {nullptr, nullptr, nullptr, nullptr};
    if (efork == nullptr) {            // host-side resource init only
        st[0] = (cudaStream_t)0;       // capture-origin stream
        cudaEventCreateWithFlags(&efork, cudaEventDisableTiming);
        for (int i = 1; i < NSLC; i++) {
            cudaStreamCreateWithFlags(&st[i], cudaStreamNonBlocking);
            cudaEventCreateWithFlags(&ejoin[i], cudaEventDisableTiming);
        }
    }

    cudaEventRecord(efork, st[0]);
    for (int i = 1; i < NSLC; i++)
        cudaStreamWaitEvent(st[i], efork, 0);

    for (int b = 0; b < Bs; b++) {
        const int s = b & (NSLC - 1);
        k_scatter<<<HW / PIX, 256, 0, st[s]>>>(x, cw, cb, offo, b, s);
        k_div<<<HW / DPIX, 128, 0, st[s]>>>(out, b, s);
    }

    for (int i = 1; i < NSLC; i++) {
        cudaEventRecord(ejoin[i], st[i]);
        cudaStreamWaitEvent(st[0], ejoin[i], 0);
    }
}